// round 14
// baseline (speedup 1.0000x reference)
#include <cuda_runtime.h>
#include <cuda_fp16.h>
#include <cstdint>

// ---------------------------------------------------------------------------
// UniformSpline log-prob (inverse rational-quadratic spline logdet)
//   x: (2097152, 8) f32   uw,uh: (8,128) f32   ud: (8,127) f32
//   out = log(0.5) - logabsdet(x), identity tails -> log(0.5)
//
// All 8 channel tables per CTA (NLUT=512 cells/channel, 86.5 KB smem) so the
// global float4 stream is CONTIGUOUS (4 cache lines per warp access, not 8).
// Cell = {e0, h|binidx(low 8 bits), delta, half2(d0,t)} -> one LDS.128 per
// element; 2/512-wide cells can hold up to TWO knots, handled by chaining
// through the bin-indexed full-f32 table sT (identity sentinels above bin 127).
// 2 CTAs x 768 threads per SM = 48 warps.
// ---------------------------------------------------------------------------

#define NCH   8
#define NBINS 128
#define NLUT  512

#define SC_OFF   0                                    // float4 sC[8][NLUT+2]
#define SC_BYTES (NCH * (NLUT + 2) * 16)
#define ST_OFF   (SC_OFF + SC_BYTES)                  // float4 sT[8][NBINS+2]
#define ST_BYTES (NCH * (NBINS + 2) * 16)
#define SE_OFF   (ST_OFF + ST_BYTES)                  // float sE[8][129]
#define SE_BYTES (NCH * (NBINS + 1) * 4)
#define SMEM_TOTAL (SE_OFF + SE_BYTES)

#define RCPA(o,a)   asm("rcp.approx.f32 %0, %1;"  : "=f"(o) : "f"(a))
#define SQRTA(o,a)  asm("sqrt.approx.f32 %0, %1;" : "=f"(o) : "f"(a))
#define LG2A(o,a)   asm("lg2.approx.f32 %0, %1;"  : "=f"(o) : "f"(a))

__device__ __forceinline__ float softplus_md(float v) {
    return 1e-3f + log1pf(expf(v));      // MIN_DERIVATIVE + softplus
}

// Per-warp (one channel) softmax(10u)+min-size cumsum -> knots in [-1,1].
__device__ __forceinline__ void edges4(const float* __restrict__ src_row,
                                       int l, float e[5]) {
    float u[4], ex[4];
#pragma unroll
    for (int k = 0; k < 4; k++) u[k] = 10.0f * src_row[l * 4 + k];
    float m = fmaxf(fmaxf(u[0], u[1]), fmaxf(u[2], u[3]));
#pragma unroll
    for (int off = 16; off; off >>= 1) m = fmaxf(m, __shfl_xor_sync(0xffffffffu, m, off));
#pragma unroll
    for (int k = 0; k < 4; k++) ex[k] = expf(u[k] - m);
    float ls = ex[0] + ex[1] + ex[2] + ex[3];

    float sc = ls;
#pragma unroll
    for (int off = 1; off < 32; off <<= 1) {
        float v = __shfl_up_sync(0xffffffffu, sc, off);
        if (l >= off) sc += v;
    }
    const float invS = 1.0f / __shfl_sync(0xffffffffu, sc, 31);
    float ce = sc - ls;

    e[0] = (l == 0) ? -1.0f
                    : 2.0f * (1e-3f * (float)(4 * l) + 0.872f * ce * invS) - 1.0f;
#pragma unroll
    for (int k = 0; k < 4; k++) {
        ce += ex[k];
        int j = l * 4 + k + 1;
        e[k + 1] = (j == NBINS) ? 1.0f
                                : 2.0f * (1e-3f * (float)j + 0.872f * ce * invS) - 1.0f;
    }
}

// One element. sCc / sTc are this element's channel rows.
__device__ __forceinline__ float spline_eval(float x,
                                             const float4* __restrict__ sCc,
                                             const float4* __restrict__ sTc) {
    const float LOG_HALF = -0.6931471805599453f;
    const float LN2      =  0.6931471805599453f;

    const float xc = fminf(fmaxf(x, -1.0f), 1.0f);
    int q = (int)fmaf(xc, 256.0f, 256.0f);    // in [0, 512]; 512 -> sentinel cell
    float4 cl = sCc[q];                        // {e0, h|bin, delta, half2(d0,t)}

    unsigned hu = __float_as_uint(cl.y);
    float h  = __uint_as_float(hu & 0xffffff00u);
    float dy = xc - cl.x;
    float dl = cl.z;
    unsigned du = __float_as_uint(cl.w);
    float2 dt = __half22float2(*reinterpret_cast<const __half2*>(&du));
    float d0 = dt.x, t = dt.y;

    if (dy > h) {                              // crossed first knot in this cell
        int idx = (int)(hu & 0xffu) + 1;
        float4 t2 = sTc[idx];                  // full-f32 {h, delta, d0, t}
        dy -= h;
        if (dy > t2.x) {                       // crossed second knot (rare)
            dy -= t2.x;
            t2 = sTc[idx + 1];
        }
        h = t2.x; dl = t2.y; d0 = t2.z; t = t2.w;
    }

    float dmd  = dl - d0;
    float dyt  = dy * t;
    float aa   = fmaf(h, dmd, dyt);
    float bb   = fmaf(h, d0, -dyt);
    float g    = dl * dy;                      // -c
    float disc = fmaxf(fmaf(bb, bb, 4.0f * (aa * g)), 0.0f);
    float s;   SQRTA(s, disc);
    float rw;  RCPA(rw, bb + s);
    float root = (g + g) * rw;
    float th   = fmaf(-root, root, root);      // root*(1-root)
    float den  = fmaf(t, th, dl);
    float pp   = fmaf(fmaf(t, root, dmd + dmd), root, d0);
    float num  = (dl * dl) * pp;
    float lgn;  LG2A(lgn, num);
    float lgd;  LG2A(lgd, den);
    float m2   = fmaf(-2.0f, lgd, lgn);        // lg2(num/den^2)
    float inside = fmaf(-LN2, m2, LOG_HALF);

    return (fabsf(x) <= 1.0f) ? inside : LOG_HALF;
}

__global__ void __launch_bounds__(768, 2)
spline_fused_kernel(const float4* __restrict__ x4, float4* __restrict__ o4, int n4,
                    const float* __restrict__ uw, const float* __restrict__ uh,
                    const float* __restrict__ ud)
{
    extern __shared__ unsigned char smem_raw[];
    float4 (*sC)[NLUT + 2]  = (float4 (*)[NLUT + 2]) (smem_raw + SC_OFF);
    float4 (*sT)[NBINS + 2] = (float4 (*)[NBINS + 2])(smem_raw + ST_OFF);
    float  (*sE)[NBINS + 1] = (float (*)[NBINS + 1]) (smem_raw + SE_OFF);

    const int tid = threadIdx.x;
    const int l   = tid & 31;

    // ---- table build: warps 0..7 -> channel = warp id ----
    if (tid < 32 * NCH) {
        const int c0 = tid >> 5;
        const float DI = logf(expf(1.0f - 1e-3f) - 1.0f);
        const float DT = softplus_md(DI);     // tail derivative == 1.0

        float ew[5], eh[5];
        edges4(uw + c0 * NBINS, l, ew);
        edges4(uh + c0 * NBINS, l, eh);

        float dd[5];
#pragma unroll
        for (int m2 = 0; m2 < 5; m2++) {
            int k = 4 * l + m2;
            dd[m2] = (k == 0 || k == NBINS) ? DT
                     : softplus_md(ud[c0 * (NBINS - 1) + k - 1]);
        }

#pragma unroll
        for (int k = 0; k < 4; k++) sE[c0][4 * l + k] = eh[k];
        if (l == 31) sE[c0][NBINS] = eh[4];

#pragma unroll
        for (int k = 0; k < 4; k++) {
            float h  = eh[k + 1] - eh[k];
            float dl = h / (ew[k + 1] - ew[k]);
            sT[c0][4 * l + k] = make_float4(h, dl, dd[k], dd[k] + dd[k + 1] - 2.0f * dl);
        }
        if (l == 31) {                        // identity sentinels (tails)
            sT[c0][NBINS]     = make_float4(1.0f, 1.0f, 1.0f, 0.0f);
            sT[c0][NBINS + 1] = make_float4(1.0f, 1.0f, 1.0f, 0.0f);
        }
    }
    __syncthreads();

    // ---- LUT: 64 threads per channel, 8 cells each ----
    if (tid < 64 * NCH) {
        const int c     = tid >> 6;
        const int cell0 = (tid & 63) * 8;
        const float* E  = &sE[c][0];
        float v = (float)cell0 * (1.0f / 256.0f) - 1.0f;
        int lo = 0;                           // largest k<=127 with E[k] <= cell start
#pragma unroll
        for (int step = 64; step; step >>= 1)
            if (lo + step <= NBINS - 1 && E[lo + step] <= v) lo += step;
        for (int q = 0; q < 8; q++) {
            float vq = (float)(cell0 + q) * (1.0f / 256.0f) - 1.0f;
            while (lo < NBINS - 1 && E[lo + 1] <= vq) lo++;
            float4 tq = sT[c][lo];            // {h, delta, d0, t}
            unsigned henc = (__float_as_uint(tq.x) & 0xffffff00u) | (unsigned)lo;
            __half2 hp = __floats2half2_rn(tq.z, tq.w);
            unsigned hu = *reinterpret_cast<unsigned*>(&hp);
            sC[c][cell0 + q] = make_float4(E[lo], __uint_as_float(henc),
                                           tq.y, __uint_as_float(hu));
        }
        if ((tid & 63) == 63) {               // sentinel cell for q == 512 (xc == 1)
            sC[c][NLUT]     = sC[c][NLUT - 1];
            sC[c][NLUT + 1] = sC[c][NLUT - 1];
        }
    }
    __syncthreads();

    // ---- main pass: contiguous float4 stream; cb = 0 or 4 by quad parity ----
    const int stride = gridDim.x * blockDim.x;

    for (int i = blockIdx.x * blockDim.x + tid; i < n4; i += stride) {
        const int cb = (i & 1) << 2;          // channel base of this quad
        const float4* sCp = &sC[cb][0];
        const float4* sTp = &sT[cb][0];
        float4 a = x4[i];
        float4 r;
        r.x = spline_eval(a.x, sCp,                  sTp);
        r.y = spline_eval(a.y, sCp + 1*(NLUT + 2),   sTp + 1*(NBINS + 2));
        r.z = spline_eval(a.z, sCp + 2*(NLUT + 2),   sTp + 2*(NBINS + 2));
        r.w = spline_eval(a.w, sCp + 3*(NLUT + 2),   sTp + 3*(NBINS + 2));
        o4[i] = r;
    }
}

// ---------------------------------------------------------------------------
extern "C" void kernel_launch(void* const* d_in, const int* in_sizes, int n_in,
                              void* d_out, int out_size)
{
    const float* x  = (const float*)d_in[0];
    const float* uw = (const float*)d_in[1];
    const float* uh = (const float*)d_in[2];
    const float* ud = (const float*)d_in[3];

    cudaFuncSetAttribute(spline_fused_kernel,
                         cudaFuncAttributeMaxDynamicSharedMemorySize, SMEM_TOTAL);

    const int n4 = out_size / 4;          // contiguous float4 stream
    spline_fused_kernel<<<296, 768, SMEM_TOTAL>>>((const float4*)x, (float4*)d_out,
                                                  n4, uw, uh, ud);
}